// round 1
// baseline (speedup 1.0000x reference)
#include <cuda_runtime.h>
#include <cfloat>
#include <math.h>

#define BS_N    4096
#define HID     2048
#define KDIM    256
#define KEY_NUM 512
#define HEAD    2
#define RANK    2
#define KNN     16
#define VDIM    512

// G = KDIM^-0.4 = 256^-0.4 = 2^-3.2
#define GW      0.10881882041201557f

// ---------------- scratch (device globals; no runtime allocation) ----------------
__device__ float g_q   [BS_N * 2 * KDIM];          // 8 MB   q = x @ Wq^T
__device__ float g_qln [BS_N * 2 * KDIM];          // 8 MB   per-half LayerNorm of q
__device__ float g_knw [2][HEAD * KEY_NUM * RANK * KDIM]; // 2x2 MB normalized keys, [n'][k] n'=h*1024+n*2+r
__device__ float g_s   [2][BS_N * HEAD * KEY_NUM * RANK]; // 2x32 MB scores s1/s2
__device__ int   g_topi[2][BS_N * HEAD * KNN];     // selected key indices i1/i2
__device__ int   g_vidx[BS_N * HEAD * KNN];        // value slot ids
__device__ float g_w   [BS_N * HEAD * KNN];        // softmax weights
__device__ float g_outv[BS_N * VDIM];              // 8 MB   weighted gathered values

// ---------------- generic fp32 GEMM:  C[m][n] = sum_k A[m*lda+k] * B[n*ldb+k] ------
// BM=BN=64, BK=16, 256 threads, 4x4 register tile. All dims are multiples of tiles.
__global__ __launch_bounds__(256) void gemm_nt(
    const float* __restrict__ A, const float* __restrict__ B, float* __restrict__ C,
    int K, int lda, int ldb, int ldc)
{
    __shared__ float As[16][64];
    __shared__ float Bs[16][64];
    const int tid = threadIdx.x;
    const int tx = tid & 15, ty = tid >> 4;
    const int m0 = blockIdx.y * 64, n0 = blockIdx.x * 64;
    const int lr = tid >> 2;            // 0..63
    const int lc = (tid & 3) << 2;      // 0,4,8,12

    const float* Ap = A + (size_t)(m0 + lr) * lda + lc;
    const float* Bp = B + (size_t)(n0 + lr) * ldb + lc;

    float acc[4][4] = {};

    for (int k0 = 0; k0 < K; k0 += 16) {
        float4 av = *(const float4*)(Ap + k0);
        float4 bv = *(const float4*)(Bp + k0);
        As[lc + 0][lr] = av.x; As[lc + 1][lr] = av.y;
        As[lc + 2][lr] = av.z; As[lc + 3][lr] = av.w;
        Bs[lc + 0][lr] = bv.x; Bs[lc + 1][lr] = bv.y;
        Bs[lc + 2][lr] = bv.z; Bs[lc + 3][lr] = bv.w;
        __syncthreads();
#pragma unroll
        for (int kk = 0; kk < 16; kk++) {
            float4 a4 = *(const float4*)&As[kk][ty * 4];
            float4 b4 = *(const float4*)&Bs[kk][tx * 4];
            float a[4] = {a4.x, a4.y, a4.z, a4.w};
            float b[4] = {b4.x, b4.y, b4.z, b4.w};
#pragma unroll
            for (int i = 0; i < 4; i++)
#pragma unroll
                for (int j = 0; j < 4; j++)
                    acc[i][j] = fmaf(a[i], b[j], acc[i][j]);
        }
        __syncthreads();
    }
#pragma unroll
    for (int i = 0; i < 4; i++) {
        float4 v = make_float4(acc[i][0], acc[i][1], acc[i][2], acc[i][3]);
        *(float4*)(C + (size_t)(m0 + ty * 4 + i) * ldc + n0 + tx * 4) = v;
    }
}

// ---------------- LayerNorm of q halves: one warp per (b, half) -------------------
__global__ void qln_kernel(const float* __restrict__ q, float* __restrict__ qln)
{
    int w = (blockIdx.x * blockDim.x + threadIdx.x) >> 5;
    int lane = threadIdx.x & 31;
    if (w >= BS_N * 2) return;
    int half = w & 1, b = w >> 1;
    const float* base = q + (size_t)b * 512 + half * 256;
    float vals[8];
    float s = 0.f;
#pragma unroll
    for (int e = 0; e < 8; e++) { vals[e] = base[lane + 32 * e]; s += vals[e]; }
#pragma unroll
    for (int off = 16; off; off >>= 1) s += __shfl_xor_sync(~0u, s, off);
    float mean = s * (1.f / 256.f);
    float vs = 0.f;
#pragma unroll
    for (int e = 0; e < 8; e++) { float d = vals[e] - mean; vs += d * d; }
#pragma unroll
    for (int off = 16; off; off >>= 1) vs += __shfl_xor_sync(~0u, vs, off);
    float scale = rsqrtf(vs * (1.f / 256.f) + 1e-5f) * GW;
    float* out = qln + (size_t)b * 512 + half * 256;
#pragma unroll
    for (int e = 0; e < 8; e++) out[lane + 32 * e] = (vals[e] - mean) * scale;
}

// ---------------- key LayerNorm over KDIM: one warp per (h,side,n,r) --------------
__global__ void keynorm_kernel(const float* __restrict__ keys,
                               float* __restrict__ knw0, float* __restrict__ knw1)
{
    int w = (blockIdx.x * blockDim.x + threadIdx.x) >> 5;
    int lane = threadIdx.x & 31;
    if (w >= HEAD * 2 * KEY_NUM * RANK) return;
    int r    = w & 1;
    int n    = (w >> 1) & (KEY_NUM - 1);
    int side = (w >> 10) & 1;
    int h    = w >> 11;
    const float* base = keys + ((size_t)(((h * 2 + side) * KEY_NUM + n)) * KDIM) * RANK + r;
    float vals[8];
    float s = 0.f;
#pragma unroll
    for (int e = 0; e < 8; e++) { vals[e] = base[(lane + 32 * e) * RANK]; s += vals[e]; }
#pragma unroll
    for (int off = 16; off; off >>= 1) s += __shfl_xor_sync(~0u, s, off);
    float mean = s * (1.f / 256.f);
    float vs = 0.f;
#pragma unroll
    for (int e = 0; e < 8; e++) { float d = vals[e] - mean; vs += d * d; }
#pragma unroll
    for (int off = 16; off; off >>= 1) vs += __shfl_xor_sync(~0u, vs, off);
    float scale = rsqrtf(vs * (1.f / 256.f) + 1e-5f) * GW;
    float* out = (side == 0 ? knw0 : knw1) + (size_t)(h * KEY_NUM * RANK + n * RANK + r) * KDIM;
#pragma unroll
    for (int e = 0; e < 8; e++) out[lane + 32 * e] = (vals[e] - mean) * scale;
}

// ---------------- top-16 of rank-1 scores: one warp per (b,h,side) ----------------
__global__ void topk_a_kernel(const float* __restrict__ s1, const float* __restrict__ s2,
                              const float* __restrict__ u, const float* __restrict__ v,
                              int* __restrict__ i1, int* __restrict__ i2)
{
    int w = (blockIdx.x * blockDim.x + threadIdx.x) >> 5;
    int lane = threadIdx.x & 31;
    if (w >= BS_N * HEAD * 2) return;
    int side = w & 1;
    int h    = (w >> 1) & 1;
    int b    = w >> 2;
    const float* sp  = (side ? s2 : s1) + (size_t)b * 2048 + h * 1024;
    const float* uvp = (side ? v : u) + h * RANK;
    float u0 = uvp[0], u1 = uvp[1];
    float av[16];
#pragma unroll
    for (int e = 0; e < 16; e++) {
        int n = lane + 32 * e;
        float2 sv = *(const float2*)(sp + n * 2);
        av[e] = sv.x * u0 + sv.y * u1;
    }
    int* out = (side ? i2 : i1) + (b * HEAD + h) * KNN;
#pragma unroll 1
    for (int t = 0; t < KNN; t++) {
        float bv = -FLT_MAX; int bi = 0x7fffffff;
#pragma unroll
        for (int e = 0; e < 16; e++) {
            int n = lane + 32 * e;
            if (av[e] > bv) { bv = av[e]; bi = n; }
        }
#pragma unroll
        for (int off = 16; off; off >>= 1) {
            float ov = __shfl_xor_sync(~0u, bv, off);
            int   oi = __shfl_xor_sync(~0u, bi, off);
            if (ov > bv || (ov == bv && oi < bi)) { bv = ov; bi = oi; }
        }
        if (lane == (bi & 31)) av[bi >> 5] = -FLT_MAX;
        if (lane == 0) out[t] = bi;
    }
}

// ------- exact tucker scores on 16x16 grid + top-16 + softmax: one warp per (b,h) --
__global__ void cand_kernel(const float* __restrict__ s1, const float* __restrict__ s2,
                            const int* __restrict__ i1, const int* __restrict__ i2,
                            const float* __restrict__ core0, const float* __restrict__ core1,
                            const int* __restrict__ shuffle_index,
                            int* __restrict__ vidx_out, float* __restrict__ w_out)
{
    int w = (blockIdx.x * blockDim.x + threadIdx.x) >> 5;
    int lane = threadIdx.x & 31;
    if (w >= BS_N * HEAD) return;
    int h = w & 1, b = w >> 1;

    float C00 = core0[h * 4 + 0] + core1[h * 4 + 0];
    float C01 = core0[h * 4 + 1] + core1[h * 4 + 1];
    float C10 = core0[h * 4 + 2] + core1[h * 4 + 2];
    float C11 = core0[h * 4 + 3] + core1[h * 4 + 3];

    // lanes 0..15 own s1g rows; lanes 16..31 own s2g rows
    int myn = 0; float g0 = 0.f, g1 = 0.f;
    if (lane < 16) {
        myn = i1[(b * HEAD + h) * KNN + lane];
        float2 sv = *(const float2*)(s1 + (size_t)b * 2048 + h * 1024 + myn * 2);
        g0 = sv.x; g1 = sv.y;
    } else {
        myn = i2[(b * HEAD + h) * KNN + (lane - 16)];
        float2 sv = *(const float2*)(s2 + (size_t)b * 2048 + h * 1024 + myn * 2);
        g0 = sv.x; g1 = sv.y;
    }
    __syncwarp();
    // t(i,:) = s1g(i,:) @ C  (valid in lanes 0..15)
    float t0  = g0 * C00 + g1 * C10;
    float t1v = g0 * C01 + g1 * C11;

    // 8 candidates per lane, cid = lane*8 + c = i*16 + j (natural flatten order)
    float cv[8];
#pragma unroll
    for (int c = 0; c < 8; c++) {
        int cid = lane * 8 + c;
        int i = cid >> 4, j = cid & 15;
        float ti0 = __shfl_sync(~0u, t0,  i);
        float ti1 = __shfl_sync(~0u, t1v, i);
        float sj0 = __shfl_sync(~0u, g0, 16 + j);
        float sj1 = __shfl_sync(~0u, g1, 16 + j);
        cv[c] = ti0 * sj0 + ti1 * sj1;
    }

    float selv = 0.f; int selc = 0;
#pragma unroll 1
    for (int t = 0; t < KNN; t++) {
        float bv = -FLT_MAX; int bc = 0x7fffffff;
#pragma unroll
        for (int c = 0; c < 8; c++) {
            int cid = lane * 8 + c;
            if (cv[c] > bv) { bv = cv[c]; bc = cid; }
        }
#pragma unroll
        for (int off = 16; off; off >>= 1) {
            float ov = __shfl_xor_sync(~0u, bv, off);
            int   oc = __shfl_xor_sync(~0u, bc, off);
            if (ov > bv || (ov == bv && oc < bc)) { bv = ov; bc = oc; }
        }
        if (lane == (bc >> 3)) cv[bc & 7] = -FLT_MAX;
        if (lane == t) { selv = bv; selc = bc; }
    }

    // stable softmax over lanes 0..15 (lane 0 holds the max: descending order)
    float mx = __shfl_sync(~0u, selv, 0);
    float e = (lane < KNN) ? expf(selv - mx) : 0.f;
    float sum = e;
#pragma unroll
    for (int off = 16; off; off >>= 1) sum += __shfl_xor_sync(~0u, sum, off);
    float wgt = e / sum;

    int ii = (selc >> 4) & 15, jj = selc & 15;
    int key_i = __shfl_sync(~0u, myn, ii);
    int key_j = __shfl_sync(~0u, myn, 16 + jj);
    if (lane < KNN) {
        int vi = shuffle_index[key_i * KEY_NUM + key_j];
        vidx_out[(b * HEAD + h) * KNN + lane] = vi;
        w_out  [(b * HEAD + h) * KNN + lane] = wgt;
    }
}

// ---------------- sparse gather + weighted combine: one block per batch row -------
__global__ __launch_bounds__(128) void gather_kernel(
    const float* __restrict__ values, const int* __restrict__ vidx,
    const float* __restrict__ wgt, float* __restrict__ outv)
{
    int b = blockIdx.x;
    __shared__ int   sidx[HEAD * KNN];
    __shared__ float sw[HEAD * KNN];
    if (threadIdx.x < HEAD * KNN) {
        sidx[threadIdx.x] = vidx[b * HEAD * KNN + threadIdx.x];
        sw[threadIdx.x]   = wgt [b * HEAD * KNN + threadIdx.x];
    }
    __syncthreads();
    int d = threadIdx.x * 4;
    float4 acc = make_float4(0.f, 0.f, 0.f, 0.f);
#pragma unroll
    for (int t = 0; t < HEAD * KNN; t++) {
        const float4 v = *(const float4*)(values + (size_t)sidx[t] * VDIM + d);
        float ww = sw[t];
        acc.x = fmaf(ww, v.x, acc.x);
        acc.y = fmaf(ww, v.y, acc.y);
        acc.z = fmaf(ww, v.z, acc.z);
        acc.w = fmaf(ww, v.w, acc.w);
    }
    *(float4*)(outv + (size_t)b * VDIM + d) = acc;
}

// -------------------------------- launcher ----------------------------------------
extern "C" void kernel_launch(void* const* d_in, const int* in_sizes, int n_in,
                              void* d_out, int out_size)
{
    const float* x        = (const float*)d_in[0];  // [4096, 2048]
    const float* q_proj_w = (const float*)d_in[1];  // [512, 2048]
    const float* keys     = (const float*)d_in[2];  // [2,2,512,256,2]
    const float* core0    = (const float*)d_in[3];  // [2,2,2]
    const float* core1    = (const float*)d_in[4];
    const float* u        = (const float*)d_in[5];  // [2,2]
    const float* v        = (const float*)d_in[6];
    const float* values   = (const float*)d_in[7];  // [262144, 512]
    const float* vproj_w  = (const float*)d_in[8];  // [2048, 512]
    const int*   shuffle  = (const int*)d_in[9];    // [262144]
    float*       out      = (float*)d_out;          // [4096, 2048]

    float *p_q, *p_qln, *p_knw, *p_s, *p_w, *p_outv;
    int *p_topi, *p_vidx;
    cudaGetSymbolAddress((void**)&p_q,    g_q);
    cudaGetSymbolAddress((void**)&p_qln,  g_qln);
    cudaGetSymbolAddress((void**)&p_knw,  g_knw);
    cudaGetSymbolAddress((void**)&p_s,    g_s);
    cudaGetSymbolAddress((void**)&p_topi, g_topi);
    cudaGetSymbolAddress((void**)&p_vidx, g_vidx);
    cudaGetSymbolAddress((void**)&p_w,    g_w);
    cudaGetSymbolAddress((void**)&p_outv, g_outv);

    float* knw0 = p_knw;
    float* knw1 = p_knw + HEAD * KEY_NUM * RANK * KDIM;
    float* s1   = p_s;
    float* s2   = p_s + (size_t)BS_N * HEAD * KEY_NUM * RANK;
    int*   i1   = p_topi;
    int*   i2   = p_topi + BS_N * HEAD * KNN;

    // 1) q = x @ Wq^T           [4096 x 512], K=2048
    gemm_nt<<<dim3(512 / 64, BS_N / 64), 256>>>(x, q_proj_w, p_q, HID, HID, HID, 512);
    // 2) per-half LayerNorm of q
    qln_kernel<<<(BS_N * 2 * 32) / 256, 256>>>(p_q, p_qln);
    // 3) key LayerNorm -> weight matrices [2048 x 256] per side
    keynorm_kernel<<<(HEAD * 2 * KEY_NUM * RANK * 32) / 256, 256>>>(keys, knw0, knw1);
    // 4) scores s1/s2 = qln_half @ knw_side^T  [4096 x 2048], K=256
    gemm_nt<<<dim3(2048 / 64, BS_N / 64), 256>>>(p_qln,       knw0, s1, KDIM, 512, KDIM, 2048);
    gemm_nt<<<dim3(2048 / 64, BS_N / 64), 256>>>(p_qln + 256, knw1, s2, KDIM, 512, KDIM, 2048);
    // 5) rank-1 approx scores + top-16 per (b,h,side)
    topk_a_kernel<<<(BS_N * HEAD * 2 * 32) / 256, 256>>>(s1, s2, u, v, i1, i2);
    // 6) exact tucker candidates + top-16 + softmax + vidx
    cand_kernel<<<(BS_N * HEAD * 32) / 256, 256>>>(s1, s2, i1, i2, core0, core1,
                                                   shuffle, p_vidx, p_w);
    // 7) sparse gather + weighted combine -> out_v [4096 x 512]
    gather_kernel<<<BS_N, 128>>>(values, p_vidx, p_w, p_outv);
    // 8) out = out_v @ vproj_w^T  [4096 x 2048], K=512
    gemm_nt<<<dim3(2048 / 64, BS_N / 64), 256>>>(p_outv, vproj_w, out, VDIM, VDIM, VDIM, 2048);
}

// round 2
// speedup vs baseline: 1.1552x; 1.1552x over previous
#include <cuda_runtime.h>
#include <cfloat>
#include <math.h>

#define BS_N    4096
#define HID     2048
#define KDIM    256
#define KEY_NUM 512
#define HEAD    2
#define RANK    2
#define KNN     16
#define VDIM    512

// G = KDIM^-0.4 = 256^-0.4 = 2^-3.2
#define GW      0.10881882041201557f

// ---------------- scratch (device globals; no runtime allocation) ----------------
__device__ float g_q   [BS_N * 2 * KDIM];                  // q = x @ Wq^T
__device__ float g_qln [BS_N * 2 * KDIM];                  // per-half LayerNorm of q
__device__ float g_knw [2][HEAD * KEY_NUM * RANK * KDIM];  // normalized keys [side][(h*512+n)*2+r][k]
__device__ float g_knu [2][HEAD * KEY_NUM * KDIM];         // u/v-contracted keys [side][h*512+n][k]
__device__ float g_a   [2][BS_N * HEAD * KEY_NUM];         // rank-1 approx scores
__device__ int   g_topi[2][BS_N * HEAD * KNN];             // selected key indices i1/i2
__device__ int   g_vidx[BS_N * HEAD * KNN];                // value slot ids
__device__ float g_w   [BS_N * HEAD * KNN];                // softmax weights
__device__ float g_outv[BS_N * VDIM];                      // weighted gathered values

// ---------------- fp32 SGEMM:  C[m][n] = sum_k A[m*lda+k] * B[n*ldb+k] ------------
// 128x128 tile, BK=8, 256 threads, 8x8 register tile, double-buffered smem.
// Requires: M%128==0, N%128==0, K%8==0.
__global__ __launch_bounds__(256) void sgemm(
    const float* __restrict__ A, const float* __restrict__ B, float* __restrict__ C,
    int K, int lda, int ldb, int ldc)
{
    __shared__ float As[2][8][128];
    __shared__ float Bs[2][8][128];
    const int tid = threadIdx.x;
    const int m0 = blockIdx.y * 128, n0 = blockIdx.x * 128;

    const int lrow = tid >> 1;          // 0..127
    const int lcol = (tid & 1) * 4;     // 0 or 4

    const float* Ap = A + (size_t)(m0 + lrow) * lda + lcol;
    const float* Bp = B + (size_t)(n0 + lrow) * ldb + lcol;

    const int tx = tid & 15;            // n-tile index
    const int ty = tid >> 4;            // m-tile index

    float acc[8][8] = {};

    // stage 0
    {
        float4 av = *(const float4*)(Ap);
        float4 bv = *(const float4*)(Bp);
        As[0][lcol + 0][lrow] = av.x; As[0][lcol + 1][lrow] = av.y;
        As[0][lcol + 2][lrow] = av.z; As[0][lcol + 3][lrow] = av.w;
        Bs[0][lcol + 0][lrow] = bv.x; Bs[0][lcol + 1][lrow] = bv.y;
        Bs[0][lcol + 2][lrow] = bv.z; Bs[0][lcol + 3][lrow] = bv.w;
    }
    __syncthreads();

    int buf = 0;
    for (int k0 = 8; k0 <= K; k0 += 8) {
        const bool more = (k0 < K);
        float4 av2, bv2;
        if (more) {
            av2 = *(const float4*)(Ap + k0);
            bv2 = *(const float4*)(Bp + k0);
        }
#pragma unroll
        for (int kk = 0; kk < 8; kk++) {
            float a[8], b[8];
            *(float4*)&a[0] = *(const float4*)&As[buf][kk][ty * 8];
            *(float4*)&a[4] = *(const float4*)&As[buf][kk][ty * 8 + 4];
            *(float4*)&b[0] = *(const float4*)&Bs[buf][kk][tx * 8];
            *(float4*)&b[4] = *(const float4*)&Bs[buf][kk][tx * 8 + 4];
#pragma unroll
            for (int i = 0; i < 8; i++)
#pragma unroll
                for (int j = 0; j < 8; j++)
                    acc[i][j] = fmaf(a[i], b[j], acc[i][j]);
        }
        if (more) {
            buf ^= 1;
            As[buf][lcol + 0][lrow] = av2.x; As[buf][lcol + 1][lrow] = av2.y;
            As[buf][lcol + 2][lrow] = av2.z; As[buf][lcol + 3][lrow] = av2.w;
            Bs[buf][lcol + 0][lrow] = bv2.x; Bs[buf][lcol + 1][lrow] = bv2.y;
            Bs[buf][lcol + 2][lrow] = bv2.z; Bs[buf][lcol + 3][lrow] = bv2.w;
            __syncthreads();
        }
    }

#pragma unroll
    for (int i = 0; i < 8; i++) {
        float* crow = C + (size_t)(m0 + ty * 8 + i) * ldc + n0 + tx * 8;
        *(float4*)(crow)     = make_float4(acc[i][0], acc[i][1], acc[i][2], acc[i][3]);
        *(float4*)(crow + 4) = make_float4(acc[i][4], acc[i][5], acc[i][6], acc[i][7]);
    }
}

// ---------------- LayerNorm of q halves: one warp per (b, half) -------------------
__global__ void qln_kernel(const float* __restrict__ q, float* __restrict__ qln)
{
    int w = (blockIdx.x * blockDim.x + threadIdx.x) >> 5;
    int lane = threadIdx.x & 31;
    if (w >= BS_N * 2) return;
    int half = w & 1, b = w >> 1;
    const float* base = q + (size_t)b * 512 + half * 256;
    float vals[8];
    float s = 0.f;
#pragma unroll
    for (int e = 0; e < 8; e++) { vals[e] = base[lane + 32 * e]; s += vals[e]; }
#pragma unroll
    for (int off = 16; off; off >>= 1) s += __shfl_xor_sync(~0u, s, off);
    float mean = s * (1.f / 256.f);
    float vs = 0.f;
#pragma unroll
    for (int e = 0; e < 8; e++) { float d = vals[e] - mean; vs += d * d; }
#pragma unroll
    for (int off = 16; off; off >>= 1) vs += __shfl_xor_sync(~0u, vs, off);
    float scale = rsqrtf(vs * (1.f / 256.f) + 1e-5f) * GW;
    float* out = qln + (size_t)b * 512 + half * 256;
#pragma unroll
    for (int e = 0; e < 8; e++) out[lane + 32 * e] = (vals[e] - mean) * scale;
}

// ---------------- key LayerNorm over KDIM: one warp per (h,side,n,r) --------------
__global__ void keynorm_kernel(const float* __restrict__ keys,
                               float* __restrict__ knw0, float* __restrict__ knw1)
{
    int w = (blockIdx.x * blockDim.x + threadIdx.x) >> 5;
    int lane = threadIdx.x & 31;
    if (w >= HEAD * 2 * KEY_NUM * RANK) return;
    int r    = w & 1;
    int n    = (w >> 1) & (KEY_NUM - 1);
    int side = (w >> 10) & 1;
    int h    = w >> 11;
    const float* base = keys + ((size_t)(((h * 2 + side) * KEY_NUM + n)) * KDIM) * RANK + r;
    float vals[8];
    float s = 0.f;
#pragma unroll
    for (int e = 0; e < 8; e++) { vals[e] = base[(lane + 32 * e) * RANK]; s += vals[e]; }
#pragma unroll
    for (int off = 16; off; off >>= 1) s += __shfl_xor_sync(~0u, s, off);
    float mean = s * (1.f / 256.f);
    float vs = 0.f;
#pragma unroll
    for (int e = 0; e < 8; e++) { float d = vals[e] - mean; vs += d * d; }
#pragma unroll
    for (int off = 16; off; off >>= 1) vs += __shfl_xor_sync(~0u, vs, off);
    float scale = rsqrtf(vs * (1.f / 256.f) + 1e-5f) * GW;
    float* out = (side == 0 ? knw0 : knw1) + (size_t)(h * KEY_NUM * RANK + n * RANK + r) * KDIM;
#pragma unroll
    for (int e = 0; e < 8; e++) out[lane + 32 * e] = (vals[e] - mean) * scale;
}

// ---------------- contract tucker u/v into normalized keys ------------------------
// knu[side][h*512+n][k] = sum_r knw[side][(h*512+n)*2+r][k] * (u|v)[h][r]
__global__ void knu_kernel(const float* __restrict__ knw0, const float* __restrict__ knw1,
                           const float* __restrict__ u, const float* __restrict__ v,
                           float* __restrict__ knu0, float* __restrict__ knu1)
{
    int g = blockIdx.x;                 // 0..2047
    int k = threadIdx.x;                // 0..255
    int side = g >> 10;
    int hn = g & 1023;
    int h = hn >> 9;
    const float* coef = (side ? v : u) + h * RANK;
    const float* knw = (side ? knw1 : knw0) + (size_t)(hn * 2) * KDIM;
    float* knu = (side ? knu1 : knu0) + (size_t)hn * KDIM;
    knu[k] = knw[k] * coef[0] + knw[KDIM + k] * coef[1];
}

// ---------------- top-16 of rank-1 scores: one warp per (b,h,side) ----------------
__global__ void topk_a_kernel(const float* __restrict__ a1, const float* __restrict__ a2,
                              int* __restrict__ i1, int* __restrict__ i2)
{
    int w = (blockIdx.x * blockDim.x + threadIdx.x) >> 5;
    int lane = threadIdx.x & 31;
    if (w >= BS_N * HEAD * 2) return;
    int side = w & 1;
    int h    = (w >> 1) & 1;
    int b    = w >> 2;
    const float* ap = (side ? a2 : a1) + (size_t)b * 1024 + h * 512;
    float av[16];
#pragma unroll
    for (int e = 0; e < 16; e++) av[e] = ap[lane + 32 * e];
    int* out = (side ? i2 : i1) + (b * HEAD + h) * KNN;
#pragma unroll 1
    for (int t = 0; t < KNN; t++) {
        float bv = -FLT_MAX; int bi = 0x7fffffff;
#pragma unroll
        for (int e = 0; e < 16; e++) {
            int n = lane + 32 * e;
            if (av[e] > bv) { bv = av[e]; bi = n; }
        }
#pragma unroll
        for (int off = 16; off; off >>= 1) {
            float ov = __shfl_xor_sync(~0u, bv, off);
            int   oi = __shfl_xor_sync(~0u, bi, off);
            if (ov > bv || (ov == bv && oi < bi)) { bv = ov; bi = oi; }
        }
        if (lane == (bi & 31)) av[bi >> 5] = -FLT_MAX;
        if (lane == 0) out[t] = bi;
    }
}

// ------- gathered exact scores + tucker candidates + top-16 + softmax --------------
// one warp per (b,h); recomputes s1g/s2g as 256-length dots against normalized keys.
__global__ void cand_kernel(const float* __restrict__ qln,
                            const float* __restrict__ knw0, const float* __restrict__ knw1,
                            const int* __restrict__ i1, const int* __restrict__ i2,
                            const float* __restrict__ core0, const float* __restrict__ core1,
                            const int* __restrict__ shuffle_index,
                            int* __restrict__ vidx_out, float* __restrict__ w_out)
{
    int w = (blockIdx.x * blockDim.x + threadIdx.x) >> 5;
    int lane = threadIdx.x & 31;
    if (w >= BS_N * HEAD) return;
    int h = w & 1, b = w >> 1;

    float C00 = core0[h * 4 + 0] + core1[h * 4 + 0];
    float C01 = core0[h * 4 + 1] + core1[h * 4 + 1];
    float C10 = core0[h * 4 + 2] + core1[h * 4 + 2];
    float C11 = core0[h * 4 + 3] + core1[h * 4 + 3];

    // lanes 0..15 own s1g rows; lanes 16..31 own s2g rows
    int myn;
    const float4* qp;
    const float4* kp;
    if (lane < 16) {
        myn = i1[(b * HEAD + h) * KNN + lane];
        qp = (const float4*)(qln + (size_t)b * 512);
        kp = (const float4*)(knw0 + (size_t)((h * KEY_NUM + myn) * 2) * KDIM);
    } else {
        myn = i2[(b * HEAD + h) * KNN + (lane - 16)];
        qp = (const float4*)(qln + (size_t)b * 512 + 256);
        kp = (const float4*)(knw1 + (size_t)((h * KEY_NUM + myn) * 2) * KDIM);
    }
    float g0 = 0.f, g1 = 0.f;
#pragma unroll 8
    for (int k4 = 0; k4 < KDIM / 4; k4++) {
        float4 qv = qp[k4];
        float4 k0v = kp[k4];
        float4 k1v = kp[KDIM / 4 + k4];
        g0 = fmaf(qv.x, k0v.x, g0); g0 = fmaf(qv.y, k0v.y, g0);
        g0 = fmaf(qv.z, k0v.z, g0); g0 = fmaf(qv.w, k0v.w, g0);
        g1 = fmaf(qv.x, k1v.x, g1); g1 = fmaf(qv.y, k1v.y, g1);
        g1 = fmaf(qv.z, k1v.z, g1); g1 = fmaf(qv.w, k1v.w, g1);
    }
    __syncwarp();

    // t(i,:) = s1g(i,:) @ C  (valid in lanes 0..15)
    float t0  = g0 * C00 + g1 * C10;
    float t1v = g0 * C01 + g1 * C11;

    // 8 candidates per lane, cid = lane*8 + c = i*16 + j (natural flatten order)
    float cv[8];
#pragma unroll
    for (int c = 0; c < 8; c++) {
        int cid = lane * 8 + c;
        int i = cid >> 4, j = cid & 15;
        float ti0 = __shfl_sync(~0u, t0,  i);
        float ti1 = __shfl_sync(~0u, t1v, i);
        float sj0 = __shfl_sync(~0u, g0, 16 + j);
        float sj1 = __shfl_sync(~0u, g1, 16 + j);
        cv[c] = ti0 * sj0 + ti1 * sj1;
    }

    float selv = 0.f; int selc = 0;
#pragma unroll 1
    for (int t = 0; t < KNN; t++) {
        float bv = -FLT_MAX; int bc = 0x7fffffff;
#pragma unroll
        for (int c = 0; c < 8; c++) {
            int cid = lane * 8 + c;
            if (cv[c] > bv) { bv = cv[c]; bc = cid; }
        }
#pragma unroll
        for (int off = 16; off; off >>= 1) {
            float ov = __shfl_xor_sync(~0u, bv, off);
            int   oc = __shfl_xor_sync(~0u, bc, off);
            if (ov > bv || (ov == bv && oc < bc)) { bv = ov; bc = oc; }
        }
        if (lane == (bc >> 3)) cv[bc & 7] = -FLT_MAX;
        if (lane == t) { selv = bv; selc = bc; }
    }

    // stable softmax over lanes 0..15 (lane 0 holds the max: descending order)
    float mx = __shfl_sync(~0u, selv, 0);
    float e = (lane < KNN) ? expf(selv - mx) : 0.f;
    float sum = e;
#pragma unroll
    for (int off = 16; off; off >>= 1) sum += __shfl_xor_sync(~0u, sum, off);
    float wgt = e / sum;

    int ii = (selc >> 4) & 15, jj = selc & 15;
    int key_i = __shfl_sync(~0u, myn, ii);
    int key_j = __shfl_sync(~0u, myn, 16 + jj);
    if (lane < KNN) {
        int vi = shuffle_index[key_i * KEY_NUM + key_j];
        vidx_out[(b * HEAD + h) * KNN + lane] = vi;
        w_out  [(b * HEAD + h) * KNN + lane] = wgt;
    }
}

// ---------------- sparse gather + weighted combine: one block per batch row -------
__global__ __launch_bounds__(128) void gather_kernel(
    const float* __restrict__ values, const int* __restrict__ vidx,
    const float* __restrict__ wgt, float* __restrict__ outv)
{
    int b = blockIdx.x;
    __shared__ int   sidx[HEAD * KNN];
    __shared__ float sw[HEAD * KNN];
    if (threadIdx.x < HEAD * KNN) {
        sidx[threadIdx.x] = vidx[b * HEAD * KNN + threadIdx.x];
        sw[threadIdx.x]   = wgt [b * HEAD * KNN + threadIdx.x];
    }
    __syncthreads();
    int d = threadIdx.x * 4;
    float4 acc = make_float4(0.f, 0.f, 0.f, 0.f);
#pragma unroll
    for (int t = 0; t < HEAD * KNN; t++) {
        const float4 v = *(const float4*)(values + (size_t)sidx[t] * VDIM + d);
        float ww = sw[t];
        acc.x = fmaf(ww, v.x, acc.x);
        acc.y = fmaf(ww, v.y, acc.y);
        acc.z = fmaf(ww, v.z, acc.z);
        acc.w = fmaf(ww, v.w, acc.w);
    }
    *(float4*)(outv + (size_t)b * VDIM + d) = acc;
}

// -------------------------------- launcher ----------------------------------------
extern "C" void kernel_launch(void* const* d_in, const int* in_sizes, int n_in,
                              void* d_out, int out_size)
{
    const float* x        = (const float*)d_in[0];  // [4096, 2048]
    const float* q_proj_w = (const float*)d_in[1];  // [512, 2048]
    const float* keys     = (const float*)d_in[2];  // [2,2,512,256,2]
    const float* core0    = (const float*)d_in[3];  // [2,2,2]
    const float* core1    = (const float*)d_in[4];
    const float* u        = (const float*)d_in[5];  // [2,2]
    const float* v        = (const float*)d_in[6];
    const float* values   = (const float*)d_in[7];  // [262144, 512]
    const float* vproj_w  = (const float*)d_in[8];  // [2048, 512]
    const int*   shuffle  = (const int*)d_in[9];    // [262144]
    float*       out      = (float*)d_out;          // [4096, 2048]

    float *p_q, *p_qln, *p_knw, *p_knu, *p_a, *p_w, *p_outv;
    int *p_topi, *p_vidx;
    cudaGetSymbolAddress((void**)&p_q,    g_q);
    cudaGetSymbolAddress((void**)&p_qln,  g_qln);
    cudaGetSymbolAddress((void**)&p_knw,  g_knw);
    cudaGetSymbolAddress((void**)&p_knu,  g_knu);
    cudaGetSymbolAddress((void**)&p_a,    g_a);
    cudaGetSymbolAddress((void**)&p_topi, g_topi);
    cudaGetSymbolAddress((void**)&p_vidx, g_vidx);
    cudaGetSymbolAddress((void**)&p_w,    g_w);
    cudaGetSymbolAddress((void**)&p_outv, g_outv);

    float* knw0 = p_knw;
    float* knw1 = p_knw + HEAD * KEY_NUM * RANK * KDIM;
    float* knu0 = p_knu;
    float* knu1 = p_knu + HEAD * KEY_NUM * KDIM;
    float* a1   = p_a;
    float* a2   = p_a + (size_t)BS_N * HEAD * KEY_NUM;
    int*   i1   = p_topi;
    int*   i2   = p_topi + BS_N * HEAD * KNN;

    // 1) q = x @ Wq^T           [4096 x 512], K=2048
    sgemm<<<dim3(512 / 128, BS_N / 128), 256>>>(x, q_proj_w, p_q, HID, HID, HID, 512);
    // 2) per-half LayerNorm of q
    qln_kernel<<<(BS_N * 2 * 32) / 256, 256>>>(p_q, p_qln);
    // 3) key LayerNorm -> normalized key rows [2048 x 256] per side
    keynorm_kernel<<<(HEAD * 2 * KEY_NUM * RANK * 32) / 256, 256>>>(keys, knw0, knw1);
    // 4) contract u/v -> knu [1024 x 256] per side
    knu_kernel<<<2 * HEAD * KEY_NUM, KDIM>>>(knw0, knw1, u, v, knu0, knu1);
    // 5) rank-1 approx scores a1/a2 = qln_half @ knu_side^T  [4096 x 1024], K=256
    sgemm<<<dim3(1024 / 128, BS_N / 128), 256>>>(p_qln,       knu0, a1, KDIM, 512, KDIM, 1024);
    sgemm<<<dim3(1024 / 128, BS_N / 128), 256>>>(p_qln + 256, knu1, a2, KDIM, 512, KDIM, 1024);
    // 6) top-16 per (b,h,side)
    topk_a_kernel<<<(BS_N * HEAD * 2 * 32) / 256, 256>>>(a1, a2, i1, i2);
    // 7) exact tucker candidates + top-16 + softmax + vidx
    cand_kernel<<<(BS_N * HEAD * 32) / 256, 256>>>(p_qln, knw0, knw1, i1, i2,
                                                   core0, core1, shuffle, p_vidx, p_w);
    // 8) sparse gather + weighted combine -> out_v [4096 x 512]
    gather_kernel<<<BS_N, 128>>>(values, p_vidx, p_w, p_outv);
    // 9) out = out_v @ vproj_w^T  [4096 x 2048], K=512
    sgemm<<<dim3(2048 / 128, BS_N / 128), 256>>>(p_outv, vproj_w, out, VDIM, VDIM, VDIM, 2048);
}

// round 4
// speedup vs baseline: 1.8867x; 1.6332x over previous
#include <cuda_runtime.h>
#include <cuda_bf16.h>
#include <cfloat>
#include <math.h>
#include <stdint.h>

#define BS_N    4096
#define HID     2048
#define KDIM    256
#define KEY_NUM 512
#define HEAD    2
#define RANK    2
#define KNN     16
#define VDIM    512

// G = KDIM^-0.4 = 256^-0.4 = 2^-3.2
#define GW      0.10881882041201557f

// ---------------- scratch (device globals; no runtime allocation) ----------------
__device__ __align__(256) float g_q   [BS_N * 2 * KDIM];
__device__ __align__(256) float g_qln [BS_N * 2 * KDIM];
__device__ __align__(256) float g_knw [HEAD * 2 * KEY_NUM * RANK * KDIM];
__device__ __align__(256) float g_a   [2][BS_N * HEAD * KEY_NUM];
__device__ int   g_topi[2][BS_N * HEAD * KNN];
__device__ int   g_vidx[BS_N * HEAD * KNN];
__device__ float g_w   [BS_N * HEAD * KNN];

// bf16 hi/lo split operands for tensor-core GEMMs
__device__ __align__(256) __nv_bfloat16 g_xhi [BS_N * HID];
__device__ __align__(256) __nv_bfloat16 g_xlo [BS_N * HID];
__device__ __align__(256) __nv_bfloat16 g_wqhi[2 * KDIM * HID];
__device__ __align__(256) __nv_bfloat16 g_wqlo[2 * KDIM * HID];
__device__ __align__(256) __nv_bfloat16 g_qlnhi[BS_N * 2 * KDIM];
__device__ __align__(256) __nv_bfloat16 g_qlnlo[BS_N * 2 * KDIM];
__device__ __align__(256) __nv_bfloat16 g_knuhi[2 * HEAD * KEY_NUM * KDIM];
__device__ __align__(256) __nv_bfloat16 g_knulo[2 * HEAD * KEY_NUM * KDIM];
__device__ __align__(256) __nv_bfloat16 g_ovhi[BS_N * VDIM];
__device__ __align__(256) __nv_bfloat16 g_ovlo[BS_N * VDIM];
__device__ __align__(256) __nv_bfloat16 g_vphi[HID * VDIM];
__device__ __align__(256) __nv_bfloat16 g_vplo[HID * VDIM];

// ================================ PTX helpers =====================================
__device__ __forceinline__ uint32_t smem_u32(const void* p) {
    return (uint32_t)__cvta_generic_to_shared(p);
}
__device__ __forceinline__ void cp16(uint32_t s, const void* g) {
    asm volatile("cp.async.cg.shared.global [%0], [%1], 16;" :: "r"(s), "l"(g) : "memory");
}
__device__ __forceinline__ void ldsm_x4(uint32_t& r0, uint32_t& r1, uint32_t& r2, uint32_t& r3,
                                        uint32_t addr) {
    asm volatile("ldmatrix.sync.aligned.m8n8.x4.shared.b16 {%0,%1,%2,%3}, [%4];"
                 : "=r"(r0), "=r"(r1), "=r"(r2), "=r"(r3) : "r"(addr));
}
__device__ __forceinline__ void mma16816(float* d, const uint32_t* a, uint32_t b0, uint32_t b1) {
    asm volatile(
        "mma.sync.aligned.m16n8k16.row.col.f32.bf16.bf16.f32 "
        "{%0,%1,%2,%3}, {%4,%5,%6,%7}, {%8,%9}, {%0,%1,%2,%3};"
        : "+f"(d[0]), "+f"(d[1]), "+f"(d[2]), "+f"(d[3])
        : "r"(a[0]), "r"(a[1]), "r"(a[2]), "r"(a[3]), "r"(b0), "r"(b1));
}

// SMEM tile geometry: 128 rows x 32 bf16, rows padded to 40 bf16 (80 B)
#define ROW_B    80
#define TILE_B   10240          // 128 * 80
#define STAGE_B  40960          // 4 tiles (Ahi, Alo, Bhi, Blo)
#define SMEM_SZ  81920          // 2 stages

// ============ bf16-split tensor-core GEMM:  C[M,N] = A[M,K] * B[N,K]^T (fp32) =====
// CTA tile 128x128, BK=32, 8 warps (4 m x 2 n), warp tile 32x64,
// cp.async double-buffered, 3-term hi/lo split accumulated in fp32.
__global__ __launch_bounds__(256, 1) void mma_gemm(
    const __nv_bfloat16* __restrict__ Ahi, const __nv_bfloat16* __restrict__ Alo,
    const __nv_bfloat16* __restrict__ Bhi, const __nv_bfloat16* __restrict__ Blo,
    float* __restrict__ C, int lda, int ldb, int ldc, int nchunks,
    int a_koff_z, int b_noff_z, long long c_off_z)
{
    extern __shared__ __align__(256) char smem[];
    const uint32_t sb = smem_u32(smem);
    const int t = threadIdx.x;
    const int wid = t >> 5, lane = t & 31;
    const int m0 = blockIdx.y * 128;
    const int nb = blockIdx.x * 128 + blockIdx.z * b_noff_z;  // B row base
    const int n0 = blockIdx.x * 128;                          // C col base
    const int aK0 = blockIdx.z * a_koff_z;
    C += (long long)blockIdx.z * c_off_z;

    const int wm = wid & 3;      // warp m position (x32)
    const int wn = wid >> 2;     // warp n position (x64)

    // per-thread load coordinates (2 reps x 4 tiles, 16B each)
    const int row0 = t >> 2, c0 = (t & 3);
    const int row1 = (t + 256) >> 2, c1 = ((t + 256) & 3);

    // ldmatrix lane address offsets (within a tile)
    const uint32_t lm_row = (uint32_t)((lane & 7) + ((lane >> 3) & 1) * 8);
    const uint32_t lm_koff = (uint32_t)((lane >> 4) * 16);

    float acc[2][8][4] = {};

    auto load_stage = [&](int i, int buf) {
        const uint32_t sbuf = sb + (uint32_t)buf * STAGE_B;
        const int kA = aK0 + i * 32;
        const int kB = i * 32;
        const __nv_bfloat16* a_hi = Ahi + (size_t)(m0 + row0) * lda + kA + c0 * 8;
        const __nv_bfloat16* a_lo = Alo + (size_t)(m0 + row0) * lda + kA + c0 * 8;
        const __nv_bfloat16* b_hi = Bhi + (size_t)(nb + row0) * ldb + kB + c0 * 8;
        const __nv_bfloat16* b_lo = Blo + (size_t)(nb + row0) * ldb + kB + c0 * 8;
        uint32_t so0 = (uint32_t)(row0 * ROW_B + c0 * 16);
        cp16(sbuf +              so0, a_hi);
        cp16(sbuf + TILE_B     + so0, a_lo);
        cp16(sbuf + 2 * TILE_B + so0, b_hi);
        cp16(sbuf + 3 * TILE_B + so0, b_lo);
        const __nv_bfloat16* a_hi2 = Ahi + (size_t)(m0 + row1) * lda + kA + c1 * 8;
        const __nv_bfloat16* a_lo2 = Alo + (size_t)(m0 + row1) * lda + kA + c1 * 8;
        const __nv_bfloat16* b_hi2 = Bhi + (size_t)(nb + row1) * ldb + kB + c1 * 8;
        const __nv_bfloat16* b_lo2 = Blo + (size_t)(nb + row1) * ldb + kB + c1 * 8;
        uint32_t so1 = (uint32_t)(row1 * ROW_B + c1 * 16);
        cp16(sbuf +              so1, a_hi2);
        cp16(sbuf + TILE_B     + so1, a_lo2);
        cp16(sbuf + 2 * TILE_B + so1, b_hi2);
        cp16(sbuf + 3 * TILE_B + so1, b_lo2);
        asm volatile("cp.async.commit_group;" ::: "memory");
    };

    load_stage(0, 0);

    for (int i = 0; i < nchunks; i++) {
        const int buf = i & 1;
        if (i + 1 < nchunks) {
            load_stage(i + 1, (i + 1) & 1);
            asm volatile("cp.async.wait_group 1;" ::: "memory");
        } else {
            asm volatile("cp.async.wait_group 0;" ::: "memory");
        }
        __syncthreads();

        const uint32_t sbuf = sb + (uint32_t)buf * STAGE_B;
        const uint32_t sAhi = sbuf;
        const uint32_t sAlo = sbuf + TILE_B;
        const uint32_t sBhi = sbuf + 2 * TILE_B;
        const uint32_t sBlo = sbuf + 3 * TILE_B;

#pragma unroll
        for (int kh = 0; kh < 2; kh++) {
            const uint32_t kb = lm_koff + kh * 32;   // byte offset for this k16
            uint32_t ah[2][4], al[2][4];
#pragma unroll
            for (int fm = 0; fm < 2; fm++) {
                uint32_t ro = (uint32_t)((wm * 32 + fm * 16) + lm_row) * ROW_B + kb;
                ldsm_x4(ah[fm][0], ah[fm][1], ah[fm][2], ah[fm][3], sAhi + ro);
                ldsm_x4(al[fm][0], al[fm][1], al[fm][2], al[fm][3], sAlo + ro);
            }
            uint32_t bh[8][2], bl[8][2];
#pragma unroll
            for (int f = 0; f < 4; f++) {
                uint32_t ro = (uint32_t)((wn * 64 + f * 16) + lm_row) * ROW_B + kb;
                uint32_t r0, r1, r2, r3;
                ldsm_x4(r0, r1, r2, r3, sBhi + ro);
                bh[f * 2][0] = r0; bh[f * 2][1] = r2;
                bh[f * 2 + 1][0] = r1; bh[f * 2 + 1][1] = r3;
                ldsm_x4(r0, r1, r2, r3, sBlo + ro);
                bl[f * 2][0] = r0; bl[f * 2][1] = r2;
                bl[f * 2 + 1][0] = r1; bl[f * 2 + 1][1] = r3;
            }
#pragma unroll
            for (int fm = 0; fm < 2; fm++)
#pragma unroll
                for (int fn = 0; fn < 8; fn++) {
                    mma16816(acc[fm][fn], ah[fm], bh[fn][0], bh[fn][1]);
                    mma16816(acc[fm][fn], ah[fm], bl[fn][0], bl[fn][1]);
                    mma16816(acc[fm][fn], al[fm], bh[fn][0], bh[fn][1]);
                }
        }
        __syncthreads();
    }

    // ---- epilogue: direct fp32 stores ----
    const int er = lane >> 2, ec = (lane & 3) * 2;
#pragma unroll
    for (int fm = 0; fm < 2; fm++) {
        const int row = m0 + wm * 32 + fm * 16 + er;
#pragma unroll
        for (int fn = 0; fn < 8; fn++) {
            const int col = n0 + wn * 64 + fn * 8 + ec;
            *(float2*)(C + (size_t)row * ldc + col) =
                make_float2(acc[fm][fn][0], acc[fm][fn][1]);
            *(float2*)(C + (size_t)(row + 8) * ldc + col) =
                make_float2(acc[fm][fn][2], acc[fm][fn][3]);
        }
    }
}

// ---------------- fp32 -> (bf16 hi, bf16 lo) elementwise split --------------------
__global__ void conv_kernel(const float* __restrict__ in,
                            __nv_bfloat16* __restrict__ hi, __nv_bfloat16* __restrict__ lo,
                            int n4)
{
    int i = blockIdx.x * blockDim.x + threadIdx.x;
    if (i >= n4) return;
    float4 v = ((const float4*)in)[i];
    __nv_bfloat16 h0 = __float2bfloat16(v.x), h1 = __float2bfloat16(v.y);
    __nv_bfloat16 h2 = __float2bfloat16(v.z), h3 = __float2bfloat16(v.w);
    __nv_bfloat16 l0 = __float2bfloat16(v.x - __bfloat162float(h0));
    __nv_bfloat16 l1 = __float2bfloat16(v.y - __bfloat162float(h1));
    __nv_bfloat16 l2 = __float2bfloat16(v.z - __bfloat162float(h2));
    __nv_bfloat16 l3 = __float2bfloat16(v.w - __bfloat162float(h3));
    ((__nv_bfloat162*)hi)[i * 2 + 0] = __nv_bfloat162(h0, h1);
    ((__nv_bfloat162*)hi)[i * 2 + 1] = __nv_bfloat162(h2, h3);
    ((__nv_bfloat162*)lo)[i * 2 + 0] = __nv_bfloat162(l0, l1);
    ((__nv_bfloat162*)lo)[i * 2 + 1] = __nv_bfloat162(l2, l3);
}

// ---------------- LayerNorm of q halves (fp32 out + bf16 hi/lo out) ---------------
__global__ void qln_kernel(const float* __restrict__ q, float* __restrict__ qln,
                           __nv_bfloat16* __restrict__ qhi, __nv_bfloat16* __restrict__ qlo)
{
    int w = (blockIdx.x * blockDim.x + threadIdx.x) >> 5;
    int lane = threadIdx.x & 31;
    if (w >= BS_N * 2) return;
    int half = w & 1, b = w >> 1;
    const float* base = q + (size_t)b * 512 + half * 256;
    float vals[8];
    float s = 0.f;
#pragma unroll
    for (int e = 0; e < 8; e++) { vals[e] = base[lane + 32 * e]; s += vals[e]; }
#pragma unroll
    for (int off = 16; off; off >>= 1) s += __shfl_xor_sync(~0u, s, off);
    float mean = s * (1.f / 256.f);
    float vs = 0.f;
#pragma unroll
    for (int e = 0; e < 8; e++) { float d = vals[e] - mean; vs += d * d; }
#pragma unroll
    for (int off = 16; off; off >>= 1) vs += __shfl_xor_sync(~0u, vs, off);
    float scale = rsqrtf(vs * (1.f / 256.f) + 1e-5f) * GW;
    size_t ob = (size_t)b * 512 + half * 256;
#pragma unroll
    for (int e = 0; e < 8; e++) {
        float o = (vals[e] - mean) * scale;
        qln[ob + lane + 32 * e] = o;
        __nv_bfloat16 h = __float2bfloat16(o);
        qhi[ob + lane + 32 * e] = h;
        qlo[ob + lane + 32 * e] = __float2bfloat16(o - __bfloat162float(h));
    }
}

// ---------------- key LayerNorm over KDIM: one warp per (h,side,n,r) --------------
__global__ void keynorm_kernel(const float* __restrict__ keys, float* __restrict__ knw)
{
    int w = (blockIdx.x * blockDim.x + threadIdx.x) >> 5;
    int lane = threadIdx.x & 31;
    if (w >= HEAD * 2 * KEY_NUM * RANK) return;
    int r    = w & 1;
    int n    = (w >> 1) & (KEY_NUM - 1);
    int side = (w >> 10) & 1;
    int h    = w >> 11;
    const float* base = keys + ((size_t)(((h * 2 + side) * KEY_NUM + n)) * KDIM) * RANK + r;
    float vals[8];
    float s = 0.f;
#pragma unroll
    for (int e = 0; e < 8; e++) { vals[e] = base[(lane + 32 * e) * RANK]; s += vals[e]; }
#pragma unroll
    for (int off = 16; off; off >>= 1) s += __shfl_xor_sync(~0u, s, off);
    float mean = s * (1.f / 256.f);
    float vs = 0.f;
#pragma unroll
    for (int e = 0; e < 8; e++) { float d = vals[e] - mean; vs += d * d; }
#pragma unroll
    for (int off = 16; off; off >>= 1) vs += __shfl_xor_sync(~0u, vs, off);
    float scale = rsqrtf(vs * (1.f / 256.f) + 1e-5f) * GW;
    float* out = knw + ((size_t)side * 2048 + (size_t)((h * KEY_NUM + n) * RANK + r)) * KDIM;
#pragma unroll
    for (int e = 0; e < 8; e++) out[lane + 32 * e] = (vals[e] - mean) * scale;
}

// ------- contract tucker u/v into normalized keys -> bf16 hi/lo -------------------
__global__ void knu_kernel(const float* __restrict__ knw,
                           const float* __restrict__ u, const float* __restrict__ v,
                           __nv_bfloat16* __restrict__ khi, __nv_bfloat16* __restrict__ klo)
{
    int g = blockIdx.x;                 // 0..2047
    int k = threadIdx.x;                // 0..255
    int side = g >> 10;
    int hn = g & 1023;
    int h = hn >> 9;
    const float* coef = (side ? v : u) + h * RANK;
    const float* kn = knw + ((size_t)side * 2048 + (size_t)hn * 2) * KDIM;
    float val = kn[k] * coef[0] + kn[KDIM + k] * coef[1];
    __nv_bfloat16 hh = __float2bfloat16(val);
    khi[(size_t)g * KDIM + k] = hh;
    klo[(size_t)g * KDIM + k] = __float2bfloat16(val - __bfloat162float(hh));
}

// ---------------- top-16 of rank-1 scores: one warp per (b,h,side) ----------------
__global__ void topk_a_kernel(const float* __restrict__ a1, const float* __restrict__ a2,
                              int* __restrict__ i1, int* __restrict__ i2)
{
    int w = (blockIdx.x * blockDim.x + threadIdx.x) >> 5;
    int lane = threadIdx.x & 31;
    if (w >= BS_N * HEAD * 2) return;
    int side = w & 1;
    int h    = (w >> 1) & 1;
    int b    = w >> 2;
    const float* ap = (side ? a2 : a1) + (size_t)b * 1024 + h * 512;
    float av[16];
#pragma unroll
    for (int e = 0; e < 16; e++) av[e] = ap[lane + 32 * e];
    int* out = (side ? i2 : i1) + (b * HEAD + h) * KNN;
#pragma unroll 1
    for (int t = 0; t < KNN; t++) {
        float bv = -FLT_MAX; int bi = 0x7fffffff;
#pragma unroll
        for (int e = 0; e < 16; e++) {
            int n = lane + 32 * e;
            if (av[e] > bv) { bv = av[e]; bi = n; }
        }
#pragma unroll
        for (int off = 16; off; off >>= 1) {
            float ov = __shfl_xor_sync(~0u, bv, off);
            int   oi = __shfl_xor_sync(~0u, bi, off);
            if (ov > bv || (ov == bv && oi < bi)) { bv = ov; bi = oi; }
        }
        if (lane == (bi & 31)) av[bi >> 5] = -FLT_MAX;
        if (lane == 0) out[t] = bi;
    }
}

// ------- gathered exact scores + tucker candidates + top-16 + softmax --------------
__global__ void cand_kernel(const float* __restrict__ qln,
                            const float* __restrict__ knw,
                            const int* __restrict__ i1, const int* __restrict__ i2,
                            const float* __restrict__ core0, const float* __restrict__ core1,
                            const int* __restrict__ shuffle_index,
                            int* __restrict__ vidx_out, float* __restrict__ w_out)
{
    int w = (blockIdx.x * blockDim.x + threadIdx.x) >> 5;
    int lane = threadIdx.x & 31;
    if (w >= BS_N * HEAD) return;
    int h = w & 1, b = w >> 1;

    float C00 = core0[h * 4 + 0] + core1[h * 4 + 0];
    float C01 = core0[h * 4 + 1] + core1[h * 4 + 1];
    float C10 = core0[h * 4 + 2] + core1[h * 4 + 2];
    float C11 = core0[h * 4 + 3] + core1[h * 4 + 3];

    int myn;
    const float4* qp;
    const float4* kp;
    if (lane < 16) {
        myn = i1[(b * HEAD + h) * KNN + lane];
        qp = (const float4*)(qln + (size_t)b * 512);
        kp = (const float4*)(knw + (size_t)((h * KEY_NUM + myn) * 2) * KDIM);
    } else {
        myn = i2[(b * HEAD + h) * KNN + (lane - 16)];
        qp = (const float4*)(qln + (size_t)b * 512 + 256);
        kp = (const float4*)(knw + (size_t)2048 * KDIM + (size_t)((h * KEY_NUM + myn) * 2) * KDIM);
    }
    float g0 = 0.f, g1 = 0.f;
#pragma unroll 8
    for (int k4 = 0; k4 < KDIM / 4; k4++) {
        float4 qv = qp[k4];
        float4 k0v = kp[k4];
        float4 k1v = kp[KDIM / 4 + k4];
        g0 = fmaf(qv.x, k0v.x, g0); g0 = fmaf(qv.y, k0v.y, g0);
        g0 = fmaf(qv.z, k0v.z, g0); g0 = fmaf(qv.w, k0v.w, g0);
        g1 = fmaf(qv.x, k1v.x, g1); g1 = fmaf(qv.y, k1v.y, g1);
        g1 = fmaf(qv.z, k1v.z, g1); g1 = fmaf(qv.w, k1v.w, g1);
    }
    __syncwarp();

    float t0  = g0 * C00 + g1 * C10;
    float t1v = g0 * C01 + g1 * C11;

    float cv[8];
#pragma unroll
    for (int c = 0; c < 8; c++) {
        int cid = lane * 8 + c;
        int i = cid >> 4, j = cid & 15;
        float ti0 = __shfl_sync(~0u, t0,  i);
        float ti1 = __shfl_sync(~0u, t1v, i);
        float sj0 = __shfl_sync(~0u, g0, 16 + j);
        float sj1 = __shfl_sync(~0u, g1, 16 + j);
        cv[c] = ti0 * sj0 + ti1 * sj1;
    }

    float selv = 0.f; int selc = 0;
#pragma unroll 1
    for (int t = 0; t < KNN; t++) {
        float bv = -FLT_MAX; int bc = 0x7fffffff;
#pragma unroll
        for (int c = 0; c < 8; c++) {
            int cid = lane * 8 + c;
            if (cv[c] > bv) { bv = cv[c]; bc = cid; }
        }
#pragma unroll
        for (int off = 16; off; off >>= 1) {
            float ov = __shfl_xor_sync(~0u, bv, off);
            int   oc = __shfl_xor_sync(~0u, bc, off);
            if (ov > bv || (ov == bv && oc < bc)) { bv = ov; bc = oc; }
        }
        if (lane == (bc >> 3)) cv[bc & 7] = -FLT_MAX;
        if (lane == t) { selv = bv; selc = bc; }
    }

    float mx = __shfl_sync(~0u, selv, 0);
    float e = (lane < KNN) ? expf(selv - mx) : 0.f;
    float sum = e;
#pragma unroll
    for (int off = 16; off; off >>= 1) sum += __shfl_xor_sync(~0u, sum, off);
    float wgt = e / sum;

    int ii = (selc >> 4) & 15, jj = selc & 15;
    int key_i = __shfl_sync(~0u, myn, ii);
    int key_j = __shfl_sync(~0u, myn, 16 + jj);
    if (lane < KNN) {
        int vi = shuffle_index[key_i * KEY_NUM + key_j];
        vidx_out[(b * HEAD + h) * KNN + lane] = vi;
        w_out  [(b * HEAD + h) * KNN + lane] = wgt;
    }
}

// ------- sparse gather + weighted combine -> bf16 hi/lo out_v ---------------------
__global__ __launch_bounds__(128) void gather_kernel(
    const float* __restrict__ values, const int* __restrict__ vidx,
    const float* __restrict__ wgt,
    __nv_bfloat16* __restrict__ ovhi, __nv_bfloat16* __restrict__ ovlo)
{
    int b = blockIdx.x;
    __shared__ int   sidx[HEAD * KNN];
    __shared__ float sw[HEAD * KNN];
    if (threadIdx.x < HEAD * KNN) {
        sidx[threadIdx.x] = vidx[b * HEAD * KNN + threadIdx.x];
        sw[threadIdx.x]   = wgt [b * HEAD * KNN + threadIdx.x];
    }
    __syncthreads();
    int d = threadIdx.x * 4;
    float4 acc = make_float4(0.f, 0.f, 0.f, 0.f);
#pragma unroll
    for (int t = 0; t < HEAD * KNN; t++) {
        const float4 v = *(const float4*)(values + (size_t)sidx[t] * VDIM + d);
        float ww = sw[t];
        acc.x = fmaf(ww, v.x, acc.x);
        acc.y = fmaf(ww, v.y, acc.y);
        acc.z = fmaf(ww, v.z, acc.z);
        acc.w = fmaf(ww, v.w, acc.w);
    }
    size_t ob = (size_t)b * VDIM + d;
    __nv_bfloat16 h0 = __float2bfloat16(acc.x), h1 = __float2bfloat16(acc.y);
    __nv_bfloat16 h2 = __float2bfloat16(acc.z), h3 = __float2bfloat16(acc.w);
    ((__nv_bfloat162*)(ovhi + ob))[0] = __nv_bfloat162(h0, h1);
    ((__nv_bfloat162*)(ovhi + ob))[1] = __nv_bfloat162(h2, h3);
    ((__nv_bfloat162*)(ovlo + ob))[0] =
        __nv_bfloat162(__float2bfloat16(acc.x - __bfloat162float(h0)),
                       __float2bfloat16(acc.y - __bfloat162float(h1)));
    ((__nv_bfloat162*)(ovlo + ob))[1] =
        __nv_bfloat162(__float2bfloat16(acc.z - __bfloat162float(h2)),
                       __float2bfloat16(acc.w - __bfloat162float(h3)));
}

// -------------------------------- launcher ----------------------------------------
extern "C" void kernel_launch(void* const* d_in, const int* in_sizes, int n_in,
                              void* d_out, int out_size)
{
    const float* x        = (const float*)d_in[0];
    const float* q_proj_w = (const float*)d_in[1];
    const float* keys     = (const float*)d_in[2];
    const float* core0    = (const float*)d_in[3];
    const float* core1    = (const float*)d_in[4];
    const float* u        = (const float*)d_in[5];
    const float* v        = (const float*)d_in[6];
    const float* values   = (const float*)d_in[7];
    const float* vproj_w  = (const float*)d_in[8];
    const int*   shuffle  = (const int*)d_in[9];
    float*       out      = (float*)d_out;

    float *p_q, *p_qln, *p_knw, *p_a, *p_w;
    int *p_topi, *p_vidx;
    __nv_bfloat16 *xhi, *xlo, *wqhi, *wqlo, *qlnhi, *qlnlo, *knuhi, *knulo;
    __nv_bfloat16 *ovhi, *ovlo, *vphi, *vplo;
    cudaGetSymbolAddress((void**)&p_q,    g_q);
    cudaGetSymbolAddress((void**)&p_qln,  g_qln);
    cudaGetSymbolAddress((void**)&p_knw,  g_knw);
    cudaGetSymbolAddress((void**)&p_a,    g_a);
    cudaGetSymbolAddress((void**)&p_topi, g_topi);
    cudaGetSymbolAddress((void**)&p_vidx, g_vidx);
    cudaGetSymbolAddress((void**)&p_w,    g_w);
    cudaGetSymbolAddress((void**)&xhi,    g_xhi);
    cudaGetSymbolAddress((void**)&xlo,    g_xlo);
    cudaGetSymbolAddress((void**)&wqhi,   g_wqhi);
    cudaGetSymbolAddress((void**)&wqlo,   g_wqlo);
    cudaGetSymbolAddress((void**)&qlnhi,  g_qlnhi);
    cudaGetSymbolAddress((void**)&qlnlo,  g_qlnlo);
    cudaGetSymbolAddress((void**)&knuhi,  g_knuhi);
    cudaGetSymbolAddress((void**)&knulo,  g_knulo);
    cudaGetSymbolAddress((void**)&ovhi,   g_ovhi);
    cudaGetSymbolAddress((void**)&ovlo,   g_ovlo);
    cudaGetSymbolAddress((void**)&vphi,   g_vphi);
    cudaGetSymbolAddress((void**)&vplo,   g_vplo);

    float* a1 = p_a;
    float* a2 = p_a + (size_t)BS_N * HEAD * KEY_NUM;
    int*   i1 = p_topi;
    int*   i2 = p_topi + BS_N * HEAD * KNN;

    cudaFuncSetAttribute(mma_gemm, cudaFuncAttributeMaxDynamicSharedMemorySize, SMEM_SZ);

    // 0) fp32 -> bf16 hi/lo splits of static GEMM operands
    conv_kernel<<<(BS_N * HID / 4) / 256, 256>>>(x, xhi, xlo, BS_N * HID / 4);
    conv_kernel<<<(2 * KDIM * HID / 4) / 256, 256>>>(q_proj_w, wqhi, wqlo, 2 * KDIM * HID / 4);
    conv_kernel<<<(HID * VDIM / 4) / 256, 256>>>(vproj_w, vphi, vplo, HID * VDIM / 4);

    // 1) q = x @ Wq^T    [4096 x 512], K=2048  (64 chunks)
    mma_gemm<<<dim3(512 / 128, BS_N / 128, 1), 256, SMEM_SZ>>>(
        xhi, xlo, wqhi, wqlo, p_q, HID, HID, 512, HID / 32, 0, 0, 0LL);

    // 2) per-half LayerNorm of q (fp32 + bf16 hi/lo)
    qln_kernel<<<(BS_N * 2 * 32) / 256, 256>>>(p_q, p_qln, qlnhi, qlnlo);

    // 3) key LayerNorm
    keynorm_kernel<<<(HEAD * 2 * KEY_NUM * RANK * 32) / 256, 256>>>(keys, p_knw);

    // 4) contract u/v -> knu bf16 hi/lo [2048 x 256]
    knu_kernel<<<2 * HEAD * KEY_NUM, KDIM>>>(p_knw, u, v, knuhi, knulo);

    // 5) approx scores a = qln_half @ knu_side^T  [4096 x 1024], K=256, z=side
    mma_gemm<<<dim3(1024 / 128, BS_N / 128, 2), 256, SMEM_SZ>>>(
        qlnhi, qlnlo, knuhi, knulo, p_a, 512, KDIM, 1024, KDIM / 32,
        256, 1024, (long long)BS_N * 1024);

    // 6) top-16 per (b,h,side)
    topk_a_kernel<<<(BS_N * HEAD * 2 * 32) / 256, 256>>>(a1, a2, i1, i2);

    // 7) exact tucker candidates + top-16 + softmax + vidx
    cand_kernel<<<(BS_N * HEAD * 32) / 256, 256>>>(p_qln, p_knw, i1, i2,
                                                   core0, core1, shuffle, p_vidx, p_w);

    // 8) sparse gather + weighted combine -> bf16 hi/lo out_v [4096 x 512]
    gather_kernel<<<BS_N, 128>>>(values, p_vidx, p_w, ovhi, ovlo);

    // 9) out = out_v @ vproj_w^T  [4096 x 2048], K=512 (16 chunks)
    mma_gemm<<<dim3(2048 / 128, BS_N / 128, 1), 256, SMEM_SZ>>>(
        ovhi, ovlo, vphi, vplo, out, VDIM, VDIM, 2048, VDIM / 32, 0, 0, 0LL);
}

// round 5
// speedup vs baseline: 2.3103x; 1.2245x over previous
#include <cuda_runtime.h>
#include <cuda_bf16.h>
#include <cfloat>
#include <math.h>
#include <stdint.h>

#define BS_N    4096
#define HID     2048
#define KDIM    256
#define KEY_NUM 512
#define HEAD    2
#define RANK    2
#define KNN     16
#define VDIM    512

// G = KDIM^-0.4 = 256^-0.4 = 2^-3.2
#define GW      0.10881882041201557f

// ---------------- scratch (device globals; no runtime allocation) ----------------
__device__ __align__(256) float g_q   [BS_N * 2 * KDIM];
__device__ __align__(256) float g_qln [BS_N * 2 * KDIM];
__device__ __align__(256) float g_knw [HEAD * 2 * KEY_NUM * RANK * KDIM];
__device__ __align__(256) float g_a   [2][BS_N * HEAD * KEY_NUM];
__device__ int   g_topi[2][BS_N * HEAD * KNN];
__device__ int   g_vidx[BS_N * HEAD * KNN];
__device__ float g_w   [BS_N * HEAD * KNN];

// bf16 hi/lo split operands for tensor-core GEMMs
__device__ __align__(256) __nv_bfloat16 g_xhi [BS_N * HID];
__device__ __align__(256) __nv_bfloat16 g_xlo [BS_N * HID];
__device__ __align__(256) __nv_bfloat16 g_wqhi[2 * KDIM * HID];
__device__ __align__(256) __nv_bfloat16 g_wqlo[2 * KDIM * HID];
__device__ __align__(256) __nv_bfloat16 g_qlnhi[BS_N * 2 * KDIM];
__device__ __align__(256) __nv_bfloat16 g_qlnlo[BS_N * 2 * KDIM];
__device__ __align__(256) __nv_bfloat16 g_knuhi[2 * HEAD * KEY_NUM * KDIM];
__device__ __align__(256) __nv_bfloat16 g_knulo[2 * HEAD * KEY_NUM * KDIM];
__device__ __align__(256) __nv_bfloat16 g_ovhi[BS_N * VDIM];
__device__ __align__(256) __nv_bfloat16 g_ovlo[BS_N * VDIM];
__device__ __align__(256) __nv_bfloat16 g_vphi[HID * VDIM];
__device__ __align__(256) __nv_bfloat16 g_vplo[HID * VDIM];

// ================================ PTX helpers =====================================
__device__ __forceinline__ uint32_t smem_u32(const void* p) {
    return (uint32_t)__cvta_generic_to_shared(p);
}
__device__ __forceinline__ void cp16(uint32_t s, const void* g) {
    asm volatile("cp.async.cg.shared.global [%0], [%1], 16;" :: "r"(s), "l"(g) : "memory");
}
__device__ __forceinline__ void ldsm_x4(uint32_t& r0, uint32_t& r1, uint32_t& r2, uint32_t& r3,
                                        uint32_t addr) {
    asm volatile("ldmatrix.sync.aligned.m8n8.x4.shared.b16 {%0,%1,%2,%3}, [%4];"
                 : "=r"(r0), "=r"(r1), "=r"(r2), "=r"(r3) : "r"(addr));
}
__device__ __forceinline__ void mma16816(float* d, const uint32_t* a, uint32_t b0, uint32_t b1) {
    asm volatile(
        "mma.sync.aligned.m16n8k16.row.col.f32.bf16.bf16.f32 "
        "{%0,%1,%2,%3}, {%4,%5,%6,%7}, {%8,%9}, {%0,%1,%2,%3};"
        : "+f"(d[0]), "+f"(d[1]), "+f"(d[2]), "+f"(d[3])
        : "r"(a[0]), "r"(a[1]), "r"(a[2]), "r"(a[3]), "r"(b0), "r"(b1));
}

// SMEM tile geometry: rows x 32 bf16, rows padded to 40 bf16 (80 B)
#define ROW_B    80

// ============ bf16-split tensor-core GEMM:  C[M,N] = A[M,K] * B[N,K]^T (fp32) =====
// CTA tile BM x 128, BK=32, 8 warps, cp.async double-buffered,
// 3-term hi/lo split accumulated in fp32. 2 CTAs/SM target.
template<int BM>
__global__ __launch_bounds__(256, 2) void mma_gemm(
    const __nv_bfloat16* __restrict__ Ahi, const __nv_bfloat16* __restrict__ Alo,
    const __nv_bfloat16* __restrict__ Bhi, const __nv_bfloat16* __restrict__ Blo,
    float* __restrict__ C, int lda, int ldb, int ldc, int nchunks,
    int a_koff_z, int b_noff_z, long long c_off_z)
{
    constexpr int NW_M   = BM / 32;        // warps along m (4 or 2)
    constexpr int NW_N   = 8 / NW_M;       // warps along n (2 or 4)
    constexpr int WTN    = 128 / NW_N;     // warp tile n (64 or 32)
    constexpr int FN     = WTN / 8;        // n8 frags (8 or 4)
    constexpr int TILE_A = BM * ROW_B;
    constexpr int TILE_B2 = 128 * ROW_B;
    constexpr int STAGE  = 2 * TILE_A + 2 * TILE_B2;
    constexpr int REPS_A = (BM * 4) / 256; // 16B chunks per A tile / threads

    extern __shared__ __align__(256) char smem[];
    const uint32_t sb = smem_u32(smem);
    const int t = threadIdx.x;
    const int wid = t >> 5, lane = t & 31;
    const int m0 = blockIdx.y * BM;
    const int nb = blockIdx.x * 128 + blockIdx.z * b_noff_z;  // B row base
    const int n0 = blockIdx.x * 128;                          // C col base
    const int aK0 = blockIdx.z * a_koff_z;
    C += (long long)blockIdx.z * c_off_z;

    const int wm = wid % NW_M;
    const int wn = wid / NW_M;

    // ldmatrix lane address offsets (within a tile)
    const uint32_t lm_row = (uint32_t)((lane & 7) + ((lane >> 3) & 1) * 8);
    const uint32_t lm_koff = (uint32_t)((lane >> 4) * 16);

    float acc[2][FN][4] = {};

    auto load_stage = [&](int i, int buf) {
        const uint32_t sbuf = sb + (uint32_t)buf * STAGE;
        const int kA = aK0 + i * 32;
        const int kB = i * 32;
#pragma unroll
        for (int rep = 0; rep < REPS_A; rep++) {
            const int idx = t + rep * 256;
            const int row = idx >> 2, c = idx & 3;
            const uint32_t so = (uint32_t)(row * ROW_B + c * 16);
            cp16(sbuf +          so, Ahi + (size_t)(m0 + row) * lda + kA + c * 8);
            cp16(sbuf + TILE_A + so, Alo + (size_t)(m0 + row) * lda + kA + c * 8);
        }
#pragma unroll
        for (int rep = 0; rep < 2; rep++) {
            const int idx = t + rep * 256;
            const int row = idx >> 2, c = idx & 3;
            const uint32_t so = (uint32_t)(row * ROW_B + c * 16);
            cp16(sbuf + 2 * TILE_A +           so, Bhi + (size_t)(nb + row) * ldb + kB + c * 8);
            cp16(sbuf + 2 * TILE_A + TILE_B2 + so, Blo + (size_t)(nb + row) * ldb + kB + c * 8);
        }
        asm volatile("cp.async.commit_group;" ::: "memory");
    };

    load_stage(0, 0);

    for (int i = 0; i < nchunks; i++) {
        const int buf = i & 1;
        if (i + 1 < nchunks) {
            load_stage(i + 1, (i + 1) & 1);
            asm volatile("cp.async.wait_group 1;" ::: "memory");
        } else {
            asm volatile("cp.async.wait_group 0;" ::: "memory");
        }
        __syncthreads();

        const uint32_t sbuf = sb + (uint32_t)buf * STAGE;
        const uint32_t sAhi = sbuf;
        const uint32_t sAlo = sbuf + TILE_A;
        const uint32_t sBhi = sbuf + 2 * TILE_A;
        const uint32_t sBlo = sbuf + 2 * TILE_A + TILE_B2;

#pragma unroll
        for (int kh = 0; kh < 2; kh++) {
            const uint32_t kb = lm_koff + kh * 32;   // byte offset for this k16
            uint32_t ah[2][4], al[2][4];
#pragma unroll
            for (int fm = 0; fm < 2; fm++) {
                uint32_t ro = (uint32_t)((wm * 32 + fm * 16) + lm_row) * ROW_B + kb;
                ldsm_x4(ah[fm][0], ah[fm][1], ah[fm][2], ah[fm][3], sAhi + ro);
                ldsm_x4(al[fm][0], al[fm][1], al[fm][2], al[fm][3], sAlo + ro);
            }
#pragma unroll
            for (int f = 0; f < FN / 2; f++) {       // each f covers n16
                uint32_t ro = (uint32_t)((wn * WTN + f * 16) + lm_row) * ROW_B + kb;
                uint32_t h0, h1, h2, h3, l0, l1, l2, l3;
                ldsm_x4(h0, h1, h2, h3, sBhi + ro);
                ldsm_x4(l0, l1, l2, l3, sBlo + ro);
#pragma unroll
                for (int fm = 0; fm < 2; fm++) {
                    mma16816(acc[fm][f * 2],     ah[fm], h0, h2);
                    mma16816(acc[fm][f * 2],     ah[fm], l0, l2);
                    mma16816(acc[fm][f * 2],     al[fm], h0, h2);
                    mma16816(acc[fm][f * 2 + 1], ah[fm], h1, h3);
                    mma16816(acc[fm][f * 2 + 1], ah[fm], l1, l3);
                    mma16816(acc[fm][f * 2 + 1], al[fm], h1, h3);
                }
            }
        }
        __syncthreads();
    }

    // ---- epilogue: direct fp32 stores ----
    const int er = lane >> 2, ec = (lane & 3) * 2;
#pragma unroll
    for (int fm = 0; fm < 2; fm++) {
        const int row = m0 + wm * 32 + fm * 16 + er;
#pragma unroll
        for (int fn = 0; fn < FN; fn++) {
            const int col = n0 + wn * WTN + fn * 8 + ec;
            *(float2*)(C + (size_t)row * ldc + col) =
                make_float2(acc[fm][fn][0], acc[fm][fn][1]);
            *(float2*)(C + (size_t)(row + 8) * ldc + col) =
                make_float2(acc[fm][fn][2], acc[fm][fn][3]);
        }
    }
}

// ---------------- fp32 -> (bf16 hi, bf16 lo) elementwise split --------------------
__global__ void conv_kernel(const float* __restrict__ in,
                            __nv_bfloat16* __restrict__ hi, __nv_bfloat16* __restrict__ lo,
                            int n4)
{
    int i = blockIdx.x * blockDim.x + threadIdx.x;
    if (i >= n4) return;
    float4 v = ((const float4*)in)[i];
    __nv_bfloat16 h0 = __float2bfloat16(v.x), h1 = __float2bfloat16(v.y);
    __nv_bfloat16 h2 = __float2bfloat16(v.z), h3 = __float2bfloat16(v.w);
    __nv_bfloat16 l0 = __float2bfloat16(v.x - __bfloat162float(h0));
    __nv_bfloat16 l1 = __float2bfloat16(v.y - __bfloat162float(h1));
    __nv_bfloat16 l2 = __float2bfloat16(v.z - __bfloat162float(h2));
    __nv_bfloat16 l3 = __float2bfloat16(v.w - __bfloat162float(h3));
    ((__nv_bfloat162*)hi)[i * 2 + 0] = __nv_bfloat162(h0, h1);
    ((__nv_bfloat162*)hi)[i * 2 + 1] = __nv_bfloat162(h2, h3);
    ((__nv_bfloat162*)lo)[i * 2 + 0] = __nv_bfloat162(l0, l1);
    ((__nv_bfloat162*)lo)[i * 2 + 1] = __nv_bfloat162(l2, l3);
}

// ---------------- LayerNorm of q halves (fp32 out + bf16 hi/lo out) ---------------
__global__ void qln_kernel(const float* __restrict__ q, float* __restrict__ qln,
                           __nv_bfloat16* __restrict__ qhi, __nv_bfloat16* __restrict__ qlo)
{
    int w = (blockIdx.x * blockDim.x + threadIdx.x) >> 5;
    int lane = threadIdx.x & 31;
    if (w >= BS_N * 2) return;
    int half = w & 1, b = w >> 1;
    const float* base = q + (size_t)b * 512 + half * 256;
    float vals[8];
    float s = 0.f;
#pragma unroll
    for (int e = 0; e < 8; e++) { vals[e] = base[lane + 32 * e]; s += vals[e]; }
#pragma unroll
    for (int off = 16; off; off >>= 1) s += __shfl_xor_sync(~0u, s, off);
    float mean = s * (1.f / 256.f);
    float vs = 0.f;
#pragma unroll
    for (int e = 0; e < 8; e++) { float d = vals[e] - mean; vs += d * d; }
#pragma unroll
    for (int off = 16; off; off >>= 1) vs += __shfl_xor_sync(~0u, vs, off);
    float scale = rsqrtf(vs * (1.f / 256.f) + 1e-5f) * GW;
    size_t ob = (size_t)b * 512 + half * 256;
#pragma unroll
    for (int e = 0; e < 8; e++) {
        float o = (vals[e] - mean) * scale;
        qln[ob + lane + 32 * e] = o;
        __nv_bfloat16 h = __float2bfloat16(o);
        qhi[ob + lane + 32 * e] = h;
        qlo[ob + lane + 32 * e] = __float2bfloat16(o - __bfloat162float(h));
    }
}

// ---------------- key LayerNorm over KDIM: one warp per (h,side,n,r) --------------
__global__ void keynorm_kernel(const float* __restrict__ keys, float* __restrict__ knw)
{
    int w = (blockIdx.x * blockDim.x + threadIdx.x) >> 5;
    int lane = threadIdx.x & 31;
    if (w >= HEAD * 2 * KEY_NUM * RANK) return;
    int r    = w & 1;
    int n    = (w >> 1) & (KEY_NUM - 1);
    int side = (w >> 10) & 1;
    int h    = w >> 11;
    const float* base = keys + ((size_t)(((h * 2 + side) * KEY_NUM + n)) * KDIM) * RANK + r;
    float vals[8];
    float s = 0.f;
#pragma unroll
    for (int e = 0; e < 8; e++) { vals[e] = base[(lane + 32 * e) * RANK]; s += vals[e]; }
#pragma unroll
    for (int off = 16; off; off >>= 1) s += __shfl_xor_sync(~0u, s, off);
    float mean = s * (1.f / 256.f);
    float vs = 0.f;
#pragma unroll
    for (int e = 0; e < 8; e++) { float d = vals[e] - mean; vs += d * d; }
#pragma unroll
    for (int off = 16; off; off >>= 1) vs += __shfl_xor_sync(~0u, vs, off);
    float scale = rsqrtf(vs * (1.f / 256.f) + 1e-5f) * GW;
    float* out = knw + ((size_t)side * 2048 + (size_t)((h * KEY_NUM + n) * RANK + r)) * KDIM;
#pragma unroll
    for (int e = 0; e < 8; e++) out[lane + 32 * e] = (vals[e] - mean) * scale;
}

// ------- contract tucker u/v into normalized keys -> bf16 hi/lo -------------------
__global__ void knu_kernel(const float* __restrict__ knw,
                           const float* __restrict__ u, const float* __restrict__ v,
                           __nv_bfloat16* __restrict__ khi, __nv_bfloat16* __restrict__ klo)
{
    int g = blockIdx.x;                 // 0..2047
    int k = threadIdx.x;                // 0..255
    int side = g >> 10;
    int hn = g & 1023;
    int h = hn >> 9;
    const float* coef = (side ? v : u) + h * RANK;
    const float* kn = knw + ((size_t)side * 2048 + (size_t)hn * 2) * KDIM;
    float val = kn[k] * coef[0] + kn[KDIM + k] * coef[1];
    __nv_bfloat16 hh = __float2bfloat16(val);
    khi[(size_t)g * KDIM + k] = hh;
    klo[(size_t)g * KDIM + k] = __float2bfloat16(val - __bfloat162float(hh));
}

// ---------------- top-16 of rank-1 scores: one warp per (b,h,side) ----------------
__global__ void topk_a_kernel(const float* __restrict__ a1, const float* __restrict__ a2,
                              int* __restrict__ i1, int* __restrict__ i2)
{
    int w = (blockIdx.x * blockDim.x + threadIdx.x) >> 5;
    int lane = threadIdx.x & 31;
    if (w >= BS_N * HEAD * 2) return;
    int side = w & 1;
    int h    = (w >> 1) & 1;
    int b    = w >> 2;
    const float* ap = (side ? a2 : a1) + (size_t)b * 1024 + h * 512;
    float av[16];
#pragma unroll
    for (int e = 0; e < 16; e++) av[e] = ap[lane + 32 * e];
    int* out = (side ? i2 : i1) + (b * HEAD + h) * KNN;
#pragma unroll 1
    for (int t = 0; t < KNN; t++) {
        float bv = -FLT_MAX; int bi = 0x7fffffff;
#pragma unroll
        for (int e = 0; e < 16; e++) {
            int n = lane + 32 * e;
            if (av[e] > bv) { bv = av[e]; bi = n; }
        }
#pragma unroll
        for (int off = 16; off; off >>= 1) {
            float ov = __shfl_xor_sync(~0u, bv, off);
            int   oi = __shfl_xor_sync(~0u, bi, off);
            if (ov > bv || (ov == bv && oi < bi)) { bv = ov; bi = oi; }
        }
        if (lane == (bi & 31)) av[bi >> 5] = -FLT_MAX;
        if (lane == 0) out[t] = bi;
    }
}

// ------- gathered exact scores + tucker candidates + top-16 + softmax --------------
// one warp per (b,h); warp cooperatively (coalesced) recomputes the 32 selected
// score pairs as 256-length dots, owner-lane captures via xor-reduction broadcast.
__global__ void cand_kernel(const float* __restrict__ qln,
                            const float* __restrict__ knw,
                            const int* __restrict__ i1, const int* __restrict__ i2,
                            const float* __restrict__ core0, const float* __restrict__ core1,
                            const int* __restrict__ shuffle_index,
                            int* __restrict__ vidx_out, float* __restrict__ w_out)
{
    int w = (blockIdx.x * blockDim.x + threadIdx.x) >> 5;
    int lane = threadIdx.x & 31;
    if (w >= BS_N * HEAD) return;
    int h = w & 1, b = w >> 1;

    float C00 = core0[h * 4 + 0] + core1[h * 4 + 0];
    float C01 = core0[h * 4 + 1] + core1[h * 4 + 1];
    float C10 = core0[h * 4 + 2] + core1[h * 4 + 2];
    float C11 = core0[h * 4 + 3] + core1[h * 4 + 3];

    // q halves, distributed: lane holds float4 idx lane and lane+32 of each half
    const float4* q1 = (const float4*)(qln + (size_t)b * 512);
    const float4* q2 = q1 + 64;
    const float4 q1a = q1[lane], q1b = q1[lane + 32];
    const float4 q2a = q2[lane], q2b = q2[lane + 32];

    // selected key indices: lanes 0..15 own i1 rows, 16..31 own i2 rows
    int myn = (lane < 16) ? i1[(b * HEAD + h) * KNN + lane]
                          : i2[(b * HEAD + h) * KNN + (lane - 16)];

    const float* kbase0 = knw + (size_t)(h * KEY_NUM) * 2 * KDIM;
    const float* kbase1 = knw + (size_t)2048 * KDIM + (size_t)(h * KEY_NUM) * 2 * KDIM;

    float g0 = 0.f, g1 = 0.f;
#pragma unroll 2
    for (int r = 0; r < 32; r++) {
        int n = __shfl_sync(~0u, myn, r);
        const int side = r >> 4;
        const float4* kp = (const float4*)((side ? kbase1 : kbase0) + (size_t)n * 2 * KDIM);
        const float4 qa = side ? q2a : q1a;
        const float4 qb = side ? q2b : q1b;
        float4 k0a = kp[lane], k0b = kp[lane + 32];
        float4 k1a = kp[64 + lane], k1b = kp[64 + lane + 32];
        float p0 = qa.x * k0a.x + qa.y * k0a.y + qa.z * k0a.z + qa.w * k0a.w
                 + qb.x * k0b.x + qb.y * k0b.y + qb.z * k0b.z + qb.w * k0b.w;
        float p1 = qa.x * k1a.x + qa.y * k1a.y + qa.z * k1a.z + qa.w * k1a.w
                 + qb.x * k1b.x + qb.y * k1b.y + qb.z * k1b.z + qb.w * k1b.w;
#pragma unroll
        for (int off = 16; off; off >>= 1) {
            p0 += __shfl_xor_sync(~0u, p0, off);
            p1 += __shfl_xor_sync(~0u, p1, off);
        }
        if (lane == r) { g0 = p0; g1 = p1; }
    }
    __syncwarp();

    float t0  = g0 * C00 + g1 * C10;
    float t1v = g0 * C01 + g1 * C11;

    float cv[8];
#pragma unroll
    for (int c = 0; c < 8; c++) {
        int cid = lane * 8 + c;
        int i = cid >> 4, j = cid & 15;
        float ti0 = __shfl_sync(~0u, t0,  i);
        float ti1 = __shfl_sync(~0u, t1v, i);
        float sj0 = __shfl_sync(~0u, g0, 16 + j);
        float sj1 = __shfl_sync(~0u, g1, 16 + j);
        cv[c] = ti0 * sj0 + ti1 * sj1;
    }

    float selv = 0.f; int selc = 0;
#pragma unroll 1
    for (int t = 0; t < KNN; t++) {
        float bv = -FLT_MAX; int bc = 0x7fffffff;
#pragma unroll
        for (int c = 0; c < 8; c++) {
            int cid = lane * 8 + c;
            if (cv[c] > bv) { bv = cv[c]; bc = cid; }
        }
#pragma unroll
        for (int off = 16; off; off >>= 1) {
            float ov = __shfl_xor_sync(~0u, bv, off);
            int   oc = __shfl_xor_sync(~0u, bc, off);
            if (ov > bv || (ov == bv && oc < bc)) { bv = ov; bc = oc; }
        }
        if (lane == (bc >> 3)) cv[bc & 7] = -FLT_MAX;
        if (lane == t) { selv = bv; selc = bc; }
    }

    float mx = __shfl_sync(~0u, selv, 0);
    float e = (lane < KNN) ? expf(selv - mx) : 0.f;
    float sum = e;
#pragma unroll
    for (int off = 16; off; off >>= 1) sum += __shfl_xor_sync(~0u, sum, off);
    float wgt = e / sum;

    int ii = (selc >> 4) & 15, jj = selc & 15;
    int key_i = __shfl_sync(~0u, myn, ii);
    int key_j = __shfl_sync(~0u, myn, 16 + jj);
    if (lane < KNN) {
        int vi = shuffle_index[key_i * KEY_NUM + key_j];
        vidx_out[(b * HEAD + h) * KNN + lane] = vi;
        w_out  [(b * HEAD + h) * KNN + lane] = wgt;
    }
}

// ------- sparse gather + weighted combine -> bf16 hi/lo out_v ---------------------
__global__ __launch_bounds__(128) void gather_kernel(
    const float* __restrict__ values, const int* __restrict__ vidx,
    const float* __restrict__ wgt,
    __nv_bfloat16* __restrict__ ovhi, __nv_bfloat16* __restrict__ ovlo)
{
    int b = blockIdx.x;
    __shared__ int   sidx[HEAD * KNN];
    __shared__ float sw[HEAD * KNN];
    if (threadIdx.x < HEAD * KNN) {
        sidx[threadIdx.x] = vidx[b * HEAD * KNN + threadIdx.x];
        sw[threadIdx.x]   = wgt [b * HEAD * KNN + threadIdx.x];
    }
    __syncthreads();
    int d = threadIdx.x * 4;
    float4 acc = make_float4(0.f, 0.f, 0.f, 0.f);
#pragma unroll
    for (int t = 0; t < HEAD * KNN; t++) {
        const float4 v = *(const float4*)(values + (size_t)sidx[t] * VDIM + d);
        float ww = sw[t];
        acc.x = fmaf(ww, v.x, acc.x);
        acc.y = fmaf(ww, v.y, acc.y);
        acc.z = fmaf(ww, v.z, acc.z);
        acc.w = fmaf(ww, v.w, acc.w);
    }
    size_t ob = (size_t)b * VDIM + d;
    __nv_bfloat16 h0 = __float2bfloat16(acc.x), h1 = __float2bfloat16(acc.y);
    __nv_bfloat16 h2 = __float2bfloat16(acc.z), h3 = __float2bfloat16(acc.w);
    ((__nv_bfloat162*)(ovhi + ob))[0] = __nv_bfloat162(h0, h1);
    ((__nv_bfloat162*)(ovhi + ob))[1] = __nv_bfloat162(h2, h3);
    ((__nv_bfloat162*)(ovlo + ob))[0] =
        __nv_bfloat162(__float2bfloat16(acc.x - __bfloat162float(h0)),
                       __float2bfloat16(acc.y - __bfloat162float(h1)));
    ((__nv_bfloat162*)(ovlo + ob))[1] =
        __nv_bfloat162(__float2bfloat16(acc.z - __bfloat162float(h2)),
                       __float2bfloat16(acc.w - __bfloat162float(h3)));
}

// -------------------------------- launcher ----------------------------------------
extern "C" void kernel_launch(void* const* d_in, const int* in_sizes, int n_in,
                              void* d_out, int out_size)
{
    const float* x        = (const float*)d_in[0];
    const float* q_proj_w = (const float*)d_in[1];
    const float* keys     = (const float*)d_in[2];
    const float* core0    = (const float*)d_in[3];
    const float* core1    = (const float*)d_in[4];
    const float* u        = (const float*)d_in[5];
    const float* v        = (const float*)d_in[6];
    const float* values   = (const float*)d_in[7];
    const float* vproj_w  = (const float*)d_in[8];
    const int*   shuffle  = (const int*)d_in[9];
    float*       out      = (float*)d_out;

    float *p_q, *p_qln, *p_knw, *p_a, *p_w;
    int *p_topi, *p_vidx;
    __nv_bfloat16 *xhi, *xlo, *wqhi, *wqlo, *qlnhi, *qlnlo, *knuhi, *knulo;
    __nv_bfloat16 *ovhi, *ovlo, *vphi, *vplo;
    cudaGetSymbolAddress((void**)&p_q,    g_q);
    cudaGetSymbolAddress((void**)&p_qln,  g_qln);
    cudaGetSymbolAddress((void**)&p_knw,  g_knw);
    cudaGetSymbolAddress((void**)&p_a,    g_a);
    cudaGetSymbolAddress((void**)&p_topi, g_topi);
    cudaGetSymbolAddress((void**)&p_vidx, g_vidx);
    cudaGetSymbolAddress((void**)&p_w,    g_w);
    cudaGetSymbolAddress((void**)&xhi,    g_xhi);
    cudaGetSymbolAddress((void**)&xlo,    g_xlo);
    cudaGetSymbolAddress((void**)&wqhi,   g_wqhi);
    cudaGetSymbolAddress((void**)&wqlo,   g_wqlo);
    cudaGetSymbolAddress((void**)&qlnhi,  g_qlnhi);
    cudaGetSymbolAddress((void**)&qlnlo,  g_qlnlo);
    cudaGetSymbolAddress((void**)&knuhi,  g_knuhi);
    cudaGetSymbolAddress((void**)&knulo,  g_knulo);
    cudaGetSymbolAddress((void**)&ovhi,   g_ovhi);
    cudaGetSymbolAddress((void**)&ovlo,   g_ovlo);
    cudaGetSymbolAddress((void**)&vphi,   g_vphi);
    cudaGetSymbolAddress((void**)&vplo,   g_vplo);

    float* a1 = p_a;
    float* a2 = p_a + (size_t)BS_N * HEAD * KEY_NUM;
    int*   i1 = p_topi;
    int*   i2 = p_topi + BS_N * HEAD * KNN;

    constexpr int SMEM128 = 2 * (2 * 128 * ROW_B + 2 * 128 * ROW_B);  // 81920
    constexpr int SMEM64  = 2 * (2 * 64 * ROW_B + 2 * 128 * ROW_B);   // 61440
    cudaFuncSetAttribute(mma_gemm<128>, cudaFuncAttributeMaxDynamicSharedMemorySize, SMEM128);
    cudaFuncSetAttribute(mma_gemm<64>,  cudaFuncAttributeMaxDynamicSharedMemorySize, SMEM64);

    // 0) fp32 -> bf16 hi/lo splits of static GEMM operands
    conv_kernel<<<(BS_N * HID / 4) / 256, 256>>>(x, xhi, xlo, BS_N * HID / 4);
    conv_kernel<<<(2 * KDIM * HID / 4) / 256, 256>>>(q_proj_w, wqhi, wqlo, 2 * KDIM * HID / 4);
    conv_kernel<<<(HID * VDIM / 4) / 256, 256>>>(vproj_w, vphi, vplo, HID * VDIM / 4);

    // 1) q = x @ Wq^T    [4096 x 512], K=2048  (BM=64 -> grid 256)
    mma_gemm<64><<<dim3(512 / 128, BS_N / 64, 1), 256, SMEM64>>>(
        xhi, xlo, wqhi, wqlo, p_q, HID, HID, 512, HID / 32, 0, 0, 0LL);

    // 2) per-half LayerNorm of q (fp32 + bf16 hi/lo)
    qln_kernel<<<(BS_N * 2 * 32) / 256, 256>>>(p_q, p_qln, qlnhi, qlnlo);

    // 3) key LayerNorm
    keynorm_kernel<<<(HEAD * 2 * KEY_NUM * RANK * 32) / 256, 256>>>(keys, p_knw);

    // 4) contract u/v -> knu bf16 hi/lo [2048 x 256]
    knu_kernel<<<2 * HEAD * KEY_NUM, KDIM>>>(p_knw, u, v, knuhi, knulo);

    // 5) approx scores a = qln_half @ knu_side^T  [4096 x 1024], K=256, z=side
    mma_gemm<128><<<dim3(1024 / 128, BS_N / 128, 2), 256, SMEM128>>>(
        qlnhi, qlnlo, knuhi, knulo, p_a, 512, KDIM, 1024, KDIM / 32,
        256, 1024, (long long)BS_N * 1024);

    // 6) top-16 per (b,h,side)
    topk_a_kernel<<<(BS_N * HEAD * 2 * 32) / 256, 256>>>(a1, a2, i1, i2);

    // 7) exact tucker candidates + top-16 + softmax + vidx
    cand_kernel<<<(BS_N * HEAD * 32) / 256, 256>>>(p_qln, p_knw, i1, i2,
                                                   core0, core1, shuffle, p_vidx, p_w);

    // 8) sparse gather + weighted combine -> bf16 hi/lo out_v [4096 x 512]
    gather_kernel<<<BS_N, 128>>>(values, p_vidx, p_w, ovhi, ovlo);

    // 9) out = out_v @ vproj_w^T  [4096 x 2048], K=512 (16 chunks)
    mma_gemm<128><<<dim3(2048 / 128, BS_N / 128, 1), 256, SMEM128>>>(
        ovhi, ovlo, vphi, vplo, out, VDIM, VDIM, 2048, VDIM / 32, 0, 0, 0LL);
}